// round 3
// baseline (speedup 1.0000x reference)
#include <cuda_runtime.h>

// Problem constants
#define B_TOT   1024
#define T_SEQ   128
#define NB_     13
#define H_      128
#define G4_     512
#define T_IN_   64
#define BQ      8      // batch rows per block
#define NBLOCKS 128
#define NTHREADS 256
#define SW_COLS 384    // gate rows resident in smem (j < 384); j in [384,512) streamed from L2

// Shared memory layout (in floats)
#define SW_OFF   0                    // [128][384]  W_hh^T slice       49152
#define SH_OFF   49152                // [128][8]    h  [k][b]           1024
#define SF_OFF   50176                // [8][128]    f  [b][d]           1024
#define SO_OFF   51200                // [8][128]    o  [b][d]           1024
#define SWO_OFF  52224                // [13][132]   W_out padded        1716
#define SX_OFF   53940                // [13][8]     x_t [n][b]           104 (+pad 8)
#define HT_OFF   54052                // [8][132]    h transposed        1056
#define SMEM_FLOATS 55108
#define SMEM_BYTES  (SMEM_FLOATS * 4)

// Device-global scratch (no runtime allocation allowed)
__device__ float g_WT[128 * 512];   // W_hh transposed: g_WT[k*512 + j] = W_hh[j][k]
__device__ float g_bias[512];       // b_ih + b_hh

// ---------- helpers ----------
__device__ __forceinline__ unsigned long long pk2(float v) {
    unsigned long long r;
    unsigned int u = __float_as_uint(v);
    asm("mov.b64 %0, {%1, %1};" : "=l"(r) : "r"(u));
    return r;
}
__device__ __forceinline__ void fma2(unsigned long long& a, unsigned long long b, unsigned long long c) {
    // packed 2x fp32 fma: a = b*c + a  (per 32-bit lane)
    asm("fma.rn.f32x2 %0, %1, %2, %0;" : "+l"(a) : "l"(b), "l"(c));
}
__device__ __forceinline__ float lo2(unsigned long long a) {
    return __uint_as_float((unsigned int)(a & 0xffffffffull));
}
__device__ __forceinline__ float hi2(unsigned long long a) {
    return __uint_as_float((unsigned int)(a >> 32));
}
__device__ __forceinline__ float sigm(float v) {
    return __fdividef(1.0f, 1.0f + __expf(-v));
}
__device__ __forceinline__ float tanh_(float v) {
    return __fdividef(2.0f, 1.0f + __expf(-2.0f * v)) - 1.0f;
}

// One 8-k chunk of the recurrent GEMM, with double-buffered L2 stream of the
// o-gate weight rows for threads t>=128 (j2 >= 384).
// h is read as two LDS.128 (broadcast) per k instead of four LDS.64.
__device__ __forceinline__ void gate_chunk(
    int KC, bool hi_thread, bool do_pref,
    const float* __restrict__ sW, const ulonglong2* __restrict__ sH128,
    const float* __restrict__ gw, int j1, int j2,
    float (&wb)[8], float (&wbn)[8],
    unsigned long long (&a1)[4], unsigned long long (&a2)[4])
{
    if (hi_thread && do_pref) {
        #pragma unroll
        for (int u = 0; u < 8; u++) wbn[u] = __ldg(gw + ((KC + 1) * 8 + u) * 512);
    }
    #pragma unroll
    for (int u = 0; u < 8; u++) {
        int k = KC * 8 + u;
        float w1 = sW[k * SW_COLS + j1];
        float w2 = hi_thread ? wb[u] : sW[k * SW_COLS + j2];
        unsigned long long w1p = pk2(w1), w2p = pk2(w2);
        ulonglong2 hA = sH128[k * 2];       // (h[k][0],h[k][1]) , (h[k][2],h[k][3])
        ulonglong2 hB = sH128[k * 2 + 1];   // (h[k][4],h[k][5]) , (h[k][6],h[k][7])
        fma2(a1[0], hA.x, w1p); fma2(a1[1], hA.y, w1p);
        fma2(a1[2], hB.x, w1p); fma2(a1[3], hB.y, w1p);
        fma2(a2[0], hA.x, w2p); fma2(a2[1], hA.y, w2p);
        fma2(a2[2], hB.x, w2p); fma2(a2[3], hB.y, w2p);
    }
}

// ---------- prep: transpose W_hh, fuse biases ----------
__global__ void prep_kernel(const float* __restrict__ W_hh,
                            const float* __restrict__ b_ih,
                            const float* __restrict__ b_hh)
{
    int idx = blockIdx.x * blockDim.x + threadIdx.x;
    if (idx < 512 * 128) {
        int j = idx >> 7, k = idx & 127;
        g_WT[k * 512 + j] = W_hh[j * 128 + k];
    }
    if (idx < 512) g_bias[idx] = b_ih[idx] + b_hh[idx];
}

// ---------- main persistent LSTM kernel ----------
__global__ void __launch_bounds__(NTHREADS, 1)
lstm_kernel(const float* __restrict__ x, const float* __restrict__ W_ih,
            const float* __restrict__ W_out, const float* __restrict__ b_out,
            float* __restrict__ out)
{
    extern __shared__ float sm[];
    float* sW  = sm + SW_OFF;
    float* sH  = sm + SH_OFF;
    float* sF  = sm + SF_OFF;
    float* sO  = sm + SO_OFF;
    float* sWo = sm + SWO_OFF;
    float* sX  = sm + SX_OFF;
    float* sHT = sm + HT_OFF;

    const int t  = threadIdx.x;
    const int b0 = blockIdx.x * BQ;

    // Load W_hh^T slice (j<384) into smem
    for (int i = t; i < 128 * SW_COLS; i += NTHREADS) {
        int k = i / SW_COLS, j = i - k * SW_COLS;
        sW[i] = g_WT[k * 512 + j];
    }
    // W_out with padded stride 132 (bank-conflict relief + float4 dot)
    for (int i = t; i < NB_ * H_; i += NTHREADS) {
        int n = i >> 7, d = i & 127;
        sWo[n * 132 + d] = W_out[i];
    }
    // h = 0 (both layouts)
    for (int i = t; i < H_ * BQ; i += NTHREADS) sH[i] = 0.0f;
    for (int i = t; i < BQ * 132; i += NTHREADS) sHT[i] = 0.0f;

    const int j1 = t, j2 = t + 256;
    const bool hi_thread = (t >= 128);
    const float* gw = g_WT + j2;        // streamed column for j2 >= 384

    float wih1[NB_], wih2[NB_];
    #pragma unroll
    for (int n = 0; n < NB_; n++) {
        wih1[n] = W_ih[j1 * NB_ + n];
        wih2[n] = W_ih[j2 * NB_ + n];
    }
    const float bs1 = g_bias[j1], bs2 = g_bias[j2];

    float c8[BQ];
    #pragma unroll
    for (int b = 0; b < BQ; b++) c8[b] = 0.0f;

    // readout mapping (104 threads: b = t/13, n = t%13)
    const int yb = t / NB_;
    const int yn = t - yb * NB_;
    const bool yth = (t < BQ * NB_);
    const float bo = yth ? __ldg(b_out + yn) : 0.0f;

    float xreg = 0.0f;
    if (yth) xreg = x[(b0 + yb) * (T_SEQ * NB_) + yn];   // x[:,0]

    __syncthreads();

    for (int s = 0; s < T_SEQ - 1; s++) {
        // input for this step: teacher x[:,s] for s<=64, else previous y (already in sX)
        if (s <= T_IN_ && yth) {
            sX[yn * 8 + yb] = xreg;
            if (s == 0) out[(b0 + yb) * (T_SEQ * NB_) + yn] = xreg;  // out[:,0] = x[:,0]
        }
        __syncthreads();
        if (s + 1 <= T_IN_ && yth)   // prefetch next teacher input (hidden under compute)
            xreg = x[(b0 + yb) * (T_SEQ * NB_) + (s + 1) * NB_ + yn];

        // ---- gates: a = bias + x@Wih^T + h@Whh^T (packed f32x2 over batch pairs) ----
        unsigned long long a1[4], a2[4];
        #pragma unroll
        for (int bp = 0; bp < 4; bp++) { a1[bp] = pk2(bs1); a2[bp] = pk2(bs2); }

        const ulonglong2* sX128 = (const ulonglong2*)sX;
        #pragma unroll
        for (int n = 0; n < NB_; n++) {
            unsigned long long w1p = pk2(wih1[n]), w2p = pk2(wih2[n]);
            ulonglong2 xA = sX128[n * 2];
            ulonglong2 xB = sX128[n * 2 + 1];
            fma2(a1[0], xA.x, w1p); fma2(a1[1], xA.y, w1p);
            fma2(a1[2], xB.x, w1p); fma2(a1[3], xB.y, w1p);
            fma2(a2[0], xA.x, w2p); fma2(a2[1], xA.y, w2p);
            fma2(a2[2], xB.x, w2p); fma2(a2[3], xB.y, w2p);
        }

        const ulonglong2* sH128 = (const ulonglong2*)(sm + SH_OFF);
        float wbuf0[8], wbuf1[8];
        if (hi_thread) {
            #pragma unroll
            for (int u = 0; u < 8; u++) wbuf0[u] = __ldg(gw + u * 512);
        }
        for (int kc2 = 0; kc2 < 8; kc2++) {
            gate_chunk(2 * kc2,     hi_thread, true,      sW, sH128, gw, j1, j2, wbuf0, wbuf1, a1, a2);
            gate_chunk(2 * kc2 + 1, hi_thread, kc2 < 7,   sW, sH128, gw, j1, j2, wbuf1, wbuf0, a1, a2);
        }

        // ---- activations + state update ----
        if (hi_thread) {
            // t in [128,256): owns f (j1) and o (j2) for dim d
            int d = t - 128;
            #pragma unroll
            for (int bp = 0; bp < 4; bp++) {
                sF[(2 * bp)     * 128 + d] = sigm(lo2(a1[bp]));
                sF[(2 * bp + 1) * 128 + d] = sigm(hi2(a1[bp]));
                sO[(2 * bp)     * 128 + d] = sigm(lo2(a2[bp]));
                sO[(2 * bp + 1) * 128 + d] = sigm(hi2(a2[bp]));
            }
        }
        __syncthreads();
        if (!hi_thread) {
            // t in [0,128): owns i (j1) and g (j2) for dim d; c lives in registers
            int d = t;
            float h8[BQ];
            #pragma unroll
            for (int bp = 0; bp < 4; bp++) {
                float iv0 = sigm(lo2(a1[bp])), iv1 = sigm(hi2(a1[bp]));
                float gv0 = tanh_(lo2(a2[bp])), gv1 = tanh_(hi2(a2[bp]));
                int b = 2 * bp;
                float c0 = fmaf(sF[b * 128 + d],       c8[b],     iv0 * gv0);
                float c1 = fmaf(sF[(b + 1) * 128 + d], c8[b + 1], iv1 * gv1);
                c8[b] = c0; c8[b + 1] = c1;
                h8[b]     = sO[b * 128 + d]       * tanh_(c0);
                h8[b + 1] = sO[(b + 1) * 128 + d] * tanh_(c1);
            }
            float4* sH4 = (float4*)(sm + SH_OFF);
            sH4[d * 2]     = make_float4(h8[0], h8[1], h8[2], h8[3]);
            sH4[d * 2 + 1] = make_float4(h8[4], h8[5], h8[6], h8[7]);
            // transposed copy for vectorized readout
            #pragma unroll
            for (int b = 0; b < BQ; b++) sHT[b * 132 + d] = h8[b];
        }
        __syncthreads();

        // ---- readout y = h @ W_out^T + b_out (float4 vectorized, 4 accumulators) ----
        if (yth) {
            const float4* h4 = (const float4*)(sHT + yb * 132);
            const float4* w4 = (const float4*)(sWo + yn * 132);
            float ac0 = bo, ac1 = 0.0f, ac2 = 0.0f, ac3 = 0.0f;
            #pragma unroll 8
            for (int q = 0; q < 32; q++) {
                float4 hv = h4[q];
                float4 wv = w4[q];
                ac0 = fmaf(hv.x, wv.x, ac0);
                ac1 = fmaf(hv.y, wv.y, ac1);
                ac2 = fmaf(hv.z, wv.z, ac2);
                ac3 = fmaf(hv.w, wv.w, ac3);
            }
            float yv = (ac0 + ac1) + (ac2 + ac3);
            out[(b0 + yb) * (T_SEQ * NB_) + (s + 1) * NB_ + yn] = yv;
            if (s >= T_IN_) sX[yn * 8 + yb] = yv;   // feedback for autoregressive phase
        }
        __syncthreads();
    }
}

extern "C" void kernel_launch(void* const* d_in, const int* in_sizes, int n_in,
                              void* d_out, int out_size)
{
    const float* x     = (const float*)d_in[0];
    const float* W_ih  = (const float*)d_in[1];
    const float* W_hh  = (const float*)d_in[2];
    const float* b_ih  = (const float*)d_in[3];
    const float* b_hh  = (const float*)d_in[4];
    const float* W_out = (const float*)d_in[5];
    const float* b_out = (const float*)d_in[6];
    float* out = (float*)d_out;

    cudaFuncSetAttribute(lstm_kernel, cudaFuncAttributeMaxDynamicSharedMemorySize, SMEM_BYTES);

    prep_kernel<<<256, 256>>>(W_hh, b_ih, b_hh);
    lstm_kernel<<<NBLOCKS, NTHREADS, SMEM_BYTES>>>(x, W_ih, W_out, b_out, out);
}

// round 4
// speedup vs baseline: 1.8047x; 1.8047x over previous
#include <cuda_runtime.h>

// Problem constants
#define B_TOT   1024
#define T_SEQ   128
#define NB_     13
#define H_      128
#define T_IN_   64
#define BQ      8
#define NBLOCKS 128
#define NTHREADS 512

// Shared layout (float indices, all 16B-aligned)
#define SW_OFF    0        // [96][512] W_hh^T pair-interleaved: sW[k*512+2*tt+e], e=0->j=tt, e=1->j=tt+256
#define SPART_OFF 49152    // [8][256] u64 partials from kg1 (as 4096 floats)
#define SH_OFF    53248    // [128][8] h  (k-major)             1024
#define SF_OFF    54272    // [8][128] f                        1024
#define SO_OFF    55296    // [8][128] o                        1024
#define SWO_OFF   56320    // [13][129] W_out (pad->1680)       1680
#define SX_OFF    58000    // [13][8] x_t                        104
#define SMEM_FLOATS 58104
#define SMEM_BYTES  (SMEM_FLOATS * 4)   // 232416 <= 232448

__device__ float g_WT2[128 * 512];  // pair-interleaved W_hh^T: g_WT2[k*512+2*t+e] = W_hh[(t+e*256)*128+k]
__device__ float g_bias[512];

// ---------- helpers ----------
__device__ __forceinline__ unsigned sptr(const void* p) {
    return (unsigned)__cvta_generic_to_shared(p);
}
__device__ __forceinline__ unsigned long long pk2(float v) {
    unsigned long long r;
    unsigned int u = __float_as_uint(v);
    asm("mov.b64 %0, {%1, %1};" : "=l"(r) : "r"(u));
    return r;
}
__device__ __forceinline__ void fma2(unsigned long long& a, unsigned long long b, unsigned long long c) {
    asm("fma.rn.f32x2 %0, %1, %2, %0;" : "+l"(a) : "l"(b), "l"(c));
}
__device__ __forceinline__ void add2(unsigned long long& a, unsigned long long b) {
    asm("add.rn.f32x2 %0, %0, %1;" : "+l"(a) : "l"(b));
}
// LDS.128 emitted directly into two u64 destinations (aligned pairs for fma.f32x2)
__device__ __forceinline__ void lds_v2u64(unsigned long long& a, unsigned long long& b, unsigned addr) {
    asm volatile("ld.shared.v2.u64 {%0, %1}, [%2];" : "=l"(a), "=l"(b) : "r"(addr));
}
__device__ __forceinline__ float lo2(unsigned long long a) {
    return __uint_as_float((unsigned int)(a & 0xffffffffull));
}
__device__ __forceinline__ float hi2(unsigned long long a) {
    return __uint_as_float((unsigned int)(a >> 32));
}
__device__ __forceinline__ float sigm(float v) { return __fdividef(1.0f, 1.0f + __expf(-v)); }
__device__ __forceinline__ float tanh_(float v) { return __fdividef(2.0f, 1.0f + __expf(-2.0f * v)) - 1.0f; }

// one k of the recurrent GEMM: 8 fma2 against h[k][0..7]
__device__ __forceinline__ void do_k(unsigned hb, int k, float w1, float w2,
                                     unsigned long long (&a1)[4], unsigned long long (&a2)[4])
{
    unsigned long long h01, h23, h45, h67;
    lds_v2u64(h01, h23, hb + k * 32);
    lds_v2u64(h45, h67, hb + k * 32 + 16);
    unsigned long long w1p = pk2(w1), w2p = pk2(w2);
    fma2(a1[0], h01, w1p); fma2(a1[1], h23, w1p); fma2(a1[2], h45, w1p); fma2(a1[3], h67, w1p);
    fma2(a2[0], h01, w2p); fma2(a2[1], h23, w2p); fma2(a2[2], h45, w2p); fma2(a2[3], h67, w2p);
}

// ---------- prep ----------
__global__ void prep_kernel(const float* __restrict__ W_hh,
                            const float* __restrict__ b_ih,
                            const float* __restrict__ b_hh)
{
    int idx = blockIdx.x * blockDim.x + threadIdx.x;
    if (idx < 128 * 512) {
        int k = idx >> 9, r = idx & 511;
        int tt = r >> 1, e = r & 1;
        int j = tt + (e << 8);
        g_WT2[idx] = W_hh[j * 128 + k];
    }
    if (idx < 512) g_bias[idx] = b_ih[idx] + b_hh[idx];
}

// ---------- main persistent LSTM kernel ----------
__global__ void __launch_bounds__(NTHREADS, 1)
lstm_kernel(const float* __restrict__ x, const float* __restrict__ W_ih,
            const float* __restrict__ W_out, const float* __restrict__ b_out,
            float* __restrict__ out)
{
    extern __shared__ float sm[];
    float* sW  = sm + SW_OFF;
    unsigned long long* sPart = (unsigned long long*)(sm + SPART_OFF);
    float* sH  = sm + SH_OFF;
    float* sF  = sm + SF_OFF;
    float* sO  = sm + SO_OFF;
    float* sWo = sm + SWO_OFF;
    float* sX  = sm + SX_OFF;

    const int t  = threadIdx.x;
    const int tt = t & 255;
    const int kg = t >> 8;
    const int b0 = blockIdx.x * BQ;

    // cooperative smem fill: W slab (96 k-rows, contiguous copy), W_out, h=0
    {
        const float4* src = (const float4*)g_WT2;
        float4* dst = (float4*)sW;
        for (int i = t; i < (96 * 512) / 4; i += NTHREADS) dst[i] = src[i];
        for (int i = t; i < NB_ * H_; i += NTHREADS) {
            int n = i >> 7, d = i & 127;
            sWo[n * 129 + d] = W_out[i];
        }
        for (int i = t; i < H_ * BQ; i += NTHREADS) sH[i] = 0.0f;
    }

    const unsigned hb = sptr(sH);
    const unsigned xb = sptr(sX);

    // kg1-only state: input weights + bias
    float wih1[NB_], wih2[NB_];
    float bs1 = 0.0f, bs2 = 0.0f;
    if (kg == 1) {
        #pragma unroll
        for (int n = 0; n < NB_; n++) {
            wih1[n] = W_ih[tt * NB_ + n];
            wih2[n] = W_ih[(tt + 256) * NB_ + n];
        }
        bs1 = g_bias[tt];
        bs2 = g_bias[tt + 256];
    }

    // c state on threads 0..127
    float c8[BQ];
    #pragma unroll
    for (int b = 0; b < BQ; b++) c8[b] = 0.0f;

    // readout threads
    const int yb = t / NB_;
    const int yn = t - yb * NB_;
    const bool yth = (t < BQ * NB_);
    const float bo = yth ? __ldg(b_out + yn) : 0.0f;
    const int rowx = yth ? ((b0 + yb) * (T_SEQ * NB_) + yn) : 0;

    float xreg = 0.0f;
    if (yth) {
        float x0 = x[rowx];               // x[:,0]
        sX[yn * 8 + yb] = x0;
        out[rowx] = x0;                   // out[:,0] = x[:,0]
        xreg = x[rowx + NB_];             // prefetch x[:,1]
    }
    __syncthreads();

    for (int s = 0; s < T_SEQ - 1; s++) {
        unsigned long long a1[4], a2[4];

        if (kg == 0) {
            // pure h-GEMM, k in [0,64) from smem
            #pragma unroll
            for (int bp = 0; bp < 4; bp++) { a1[bp] = 0ull; a2[bp] = 0ull; }
            #pragma unroll 1
            for (int kc = 0; kc < 8; kc++) {
                #pragma unroll
                for (int u = 0; u < 8; u++) {
                    int k = kc * 8 + u;
                    float2 wp = *(const float2*)(sW + k * 512 + 2 * tt);
                    do_k(hb, k, wp.x, wp.y, a1, a2);
                }
            }
        } else {
            // bias + x@Wih^T + h-GEMM k in [64,128)
            #pragma unroll
            for (int bp = 0; bp < 4; bp++) { a1[bp] = pk2(bs1); a2[bp] = pk2(bs2); }
            #pragma unroll
            for (int n = 0; n < NB_; n++) {
                unsigned long long x01, x23, x45, x67;
                lds_v2u64(x01, x23, xb + n * 32);
                lds_v2u64(x45, x67, xb + n * 32 + 16);
                unsigned long long w1p = pk2(wih1[n]), w2p = pk2(wih2[n]);
                fma2(a1[0], x01, w1p); fma2(a1[1], x23, w1p); fma2(a1[2], x45, w1p); fma2(a1[3], x67, w1p);
                fma2(a2[0], x01, w2p); fma2(a2[1], x23, w2p); fma2(a2[2], x45, w2p); fma2(a2[3], x67, w2p);
            }
            // k in [64,96) from smem
            #pragma unroll 1
            for (int kc = 0; kc < 4; kc++) {
                #pragma unroll
                for (int u = 0; u < 8; u++) {
                    int k = 64 + kc * 8 + u;
                    float2 wp = *(const float2*)(sW + k * 512 + 2 * tt);
                    do_k(hb, k, wp.x, wp.y, a1, a2);
                }
            }
            // k in [96,128) streamed from L2 (pair LDG.64, double-buffered x4)
            {
                const float2* gp = ((const float2*)g_WT2) + 96 * 256 + tt;
                float2 bufA[4], bufB[4];
                #pragma unroll
                for (int u = 0; u < 4; u++) bufA[u] = __ldg(gp + u * 256);
                #pragma unroll
                for (int g = 0; g < 8; g++) {
                    float2* cur = (g & 1) ? bufB : bufA;
                    float2* nxt = (g & 1) ? bufA : bufB;
                    if (g < 7) {
                        #pragma unroll
                        for (int u = 0; u < 4; u++) nxt[u] = __ldg(gp + ((g + 1) * 4 + u) * 256);
                    }
                    #pragma unroll
                    for (int u = 0; u < 4; u++)
                        do_k(hb, 96 + g * 4 + u, cur[u].x, cur[u].y, a1, a2);
                }
            }
            // publish partials (conflict-free: lane-consecutive 8B)
            #pragma unroll
            for (int bp = 0; bp < 4; bp++) {
                sPart[bp * 256 + tt]       = a1[bp];
                sPart[(4 + bp) * 256 + tt] = a2[bp];
            }
        }
        __syncthreads();   // partials ready

        if (kg == 0) {
            #pragma unroll
            for (int bp = 0; bp < 4; bp++) {
                add2(a1[bp], sPart[bp * 256 + tt]);
                add2(a2[bp], sPart[(4 + bp) * 256 + tt]);
            }
            if (tt >= 128) {
                // f (j1) and o (j2)
                int d = tt - 128;
                #pragma unroll
                for (int bp = 0; bp < 4; bp++) {
                    sF[(2 * bp)     * 128 + d] = sigm(lo2(a1[bp]));
                    sF[(2 * bp + 1) * 128 + d] = sigm(hi2(a1[bp]));
                    sO[(2 * bp)     * 128 + d] = sigm(lo2(a2[bp]));
                    sO[(2 * bp + 1) * 128 + d] = sigm(hi2(a2[bp]));
                }
            }
        }
        __syncthreads();   // f,o ready

        if (t < 128) {
            // i (j1), g (j2); c in registers
            int d = t;
            float h8[BQ];
            #pragma unroll
            for (int bp = 0; bp < 4; bp++) {
                float iv0 = sigm(lo2(a1[bp])), iv1 = sigm(hi2(a1[bp]));
                float gv0 = tanh_(lo2(a2[bp])), gv1 = tanh_(hi2(a2[bp]));
                int b = 2 * bp;
                float c0 = fmaf(sF[b * 128 + d],       c8[b],     iv0 * gv0);
                float c1 = fmaf(sF[(b + 1) * 128 + d], c8[b + 1], iv1 * gv1);
                c8[b] = c0; c8[b + 1] = c1;
                h8[b]     = sO[b * 128 + d]       * tanh_(c0);
                h8[b + 1] = sO[(b + 1) * 128 + d] * tanh_(c1);
            }
            float4* sH4 = (float4*)sH;
            sH4[d * 2]     = make_float4(h8[0], h8[1], h8[2], h8[3]);
            sH4[d * 2 + 1] = make_float4(h8[4], h8[5], h8[6], h8[7]);
        }
        __syncthreads();   // h ready

        if (yth) {
            float acc0 = bo, acc1v = 0.0f;
            #pragma unroll 4
            for (int d = 0; d < H_; d += 2) {
                acc0  = fmaf(sH[d * 8 + yb],       sWo[yn * 129 + d],     acc0);
                acc1v = fmaf(sH[(d + 1) * 8 + yb], sWo[yn * 129 + d + 1], acc1v);
            }
            float yv = acc0 + acc1v;
            int sn = s + 1;
            out[rowx + sn * NB_] = yv;
            if (sn <= T_IN_) {
                sX[yn * 8 + yb] = xreg;                       // teacher input x[:,sn]
                if (sn + 1 <= T_IN_) xreg = x[rowx + (sn + 1) * NB_];
            } else {
                sX[yn * 8 + yb] = yv;                         // autoregressive feedback
            }
        }
        __syncthreads();   // input/h stable for next step
    }
}

extern "C" void kernel_launch(void* const* d_in, const int* in_sizes, int n_in,
                              void* d_out, int out_size)
{
    const float* x     = (const float*)d_in[0];
    const float* W_ih  = (const float*)d_in[1];
    const float* W_hh  = (const float*)d_in[2];
    const float* b_ih  = (const float*)d_in[3];
    const float* b_hh  = (const float*)d_in[4];
    const float* W_out = (const float*)d_in[5];
    const float* b_out = (const float*)d_in[6];
    float* out = (float*)d_out;

    cudaFuncSetAttribute(lstm_kernel, cudaFuncAttributeMaxDynamicSharedMemorySize, SMEM_BYTES);

    prep_kernel<<<256, 256>>>(W_hh, b_ih, b_hh);
    lstm_kernel<<<NBLOCKS, NTHREADS, SMEM_BYTES>>>(x, W_ih, W_out, b_out, out);
}